// round 1
// baseline (speedup 1.0000x reference)
#include <cuda_runtime.h>
#include <cuda_bf16.h>
#include <cstdint>

// Problem constants
#define NWIN   2048   // windowed batches (B_)
#define WIN    64     // tokens per window
#define DIM    256    // channels
#define HEADS  8
#define HD     32     // head dim
#define NMASK  256    // mask windows (b % NMASK)
#define QKV_N  768    // 3*DIM
#define MROWS  (NWIN*WIN)  // 131072

// Scratch (allocation-free: __device__ globals)
__device__ float g_q[(size_t)NWIN*HEADS*WIN*HD];   // 134 MB
__device__ float g_k[(size_t)NWIN*HEADS*WIN*HD];
__device__ float g_v[(size_t)NWIN*HEADS*WIN*HD];
__device__ float g_ao[(size_t)NWIN*WIN*DIM];       // attention output (b,n,h,d) flattened

// ---------------------------------------------------------------------------
// GEMM 1: qkv = x @ qkv_w^T + qkv_b, scattered into g_q/g_k/g_v as (b,h,n,d)
// A: [131072 x 256] row-major, W: [768 x 256] row-major.
// Tile 64x64, BK=16, 256 threads, 4x4 per thread.
// ---------------------------------------------------------------------------
__global__ void qkv_gemm_kernel(const float* __restrict__ A,
                                const float* __restrict__ W,
                                const float* __restrict__ bias)
{
    const int K = DIM;
    __shared__ float As[16][64];
    __shared__ float Bs[16][64];

    const int rowBase = blockIdx.y * 64;
    const int colBase = blockIdx.x * 64;
    const int tid = threadIdx.x;
    const int tx = tid & 15;
    const int ty = tid >> 4;

    float acc[4][4] = {};

    const int r   = tid >> 2;         // 0..63
    const int kk0 = (tid & 3) << 2;   // 0,4,8,12

    for (int kb = 0; kb < K; kb += 16) {
        float4 a4 = *(const float4*)&A[(size_t)(rowBase + r) * K + kb + kk0];
        As[kk0 + 0][r] = a4.x; As[kk0 + 1][r] = a4.y;
        As[kk0 + 2][r] = a4.z; As[kk0 + 3][r] = a4.w;
        float4 b4 = *(const float4*)&W[(size_t)(colBase + r) * K + kb + kk0];
        Bs[kk0 + 0][r] = b4.x; Bs[kk0 + 1][r] = b4.y;
        Bs[kk0 + 2][r] = b4.z; Bs[kk0 + 3][r] = b4.w;
        __syncthreads();

        #pragma unroll
        for (int kk = 0; kk < 16; kk++) {
            float4 ra = *(const float4*)&As[kk][ty << 2];
            float4 rb = *(const float4*)&Bs[kk][tx << 2];
            float rav[4] = {ra.x, ra.y, ra.z, ra.w};
            float rbv[4] = {rb.x, rb.y, rb.z, rb.w};
            #pragma unroll
            for (int i = 0; i < 4; i++)
                #pragma unroll
                for (int j = 0; j < 4; j++)
                    acc[i][j] = fmaf(rav[i], rbv[j], acc[i][j]);
        }
        __syncthreads();
    }

    #pragma unroll
    for (int i = 0; i < 4; i++) {
        const int row = rowBase + (ty << 2) + i;
        const int b = row >> 6;
        const int n = row & 63;
        #pragma unroll
        for (int j = 0; j < 4; j++) {
            const int col = colBase + (tx << 2) + j;
            float c = acc[i][j] + bias[col];
            const int which = col >> 8;        // 0=q 1=k 2=v
            const int h = (col >> 5) & 7;
            const int d = col & 31;
            float* dst = (which == 0) ? g_q : (which == 1) ? g_k : g_v;
            dst[((((size_t)b * HEADS + h) * WIN) + n) * HD + d] = c;
        }
    }
}

// ---------------------------------------------------------------------------
// Attention: one block per (window b, head h). 256 threads.
// cosine attn: normalize q,k rows; q row also folds in exp(min(ls, ln100)).
// logits += rel_bias_table[rpi[i,j]][h] + mask[b%256][i][j]; softmax; A@V.
// ---------------------------------------------------------------------------
__global__ void attn_kernel(const float* __restrict__ mask,
                            const float* __restrict__ logit_scale,
                            const float* __restrict__ bias_table,
                            const int*   __restrict__ rpi)
{
    const int bh = blockIdx.x;         // b*8 + h
    const int b  = bh >> 3;
    const int h  = bh & 7;
    const int tid = threadIdx.x;

    __shared__ float qs[WIN][HD + 1];
    __shared__ float ks[WIN][HD + 1];
    __shared__ float vs[WIN][HD + 1];
    __shared__ float at[WIN][WIN];

    const size_t base = (size_t)bh * WIN * HD;
    for (int idx = tid; idx < WIN * HD; idx += 256) {
        const int n = idx >> 5, d = idx & 31;
        qs[n][d] = g_q[base + idx];
        ks[n][d] = g_k[base + idx];
        vs[n][d] = g_v[base + idx];
    }
    __syncthreads();

    const float ls = expf(fminf(logit_scale[h], 4.6051701859880914f)); // ln(100)

    // Normalize rows of q (with scale) and k.
    if (tid < 128) {
        const int rrow = tid & 63;
        float* rowp = (tid < 64) ? &qs[rrow][0] : &ks[rrow][0];
        float s = 0.f;
        #pragma unroll
        for (int d = 0; d < HD; d++) s += rowp[d] * rowp[d];
        float inv = 1.0f / fmaxf(sqrtf(s), 1e-12f);
        if (tid < 64) inv *= ls;
        #pragma unroll
        for (int d = 0; d < HD; d++) rowp[d] *= inv;
    }
    __syncthreads();

    // Logits + bias + mask
    const float* mrow = mask + (size_t)(b & (NMASK - 1)) * WIN * WIN;
    for (int e = tid; e < WIN * WIN; e += 256) {
        const int i = e >> 6, j = e & 63;
        float s = 0.f;
        #pragma unroll
        for (int d = 0; d < HD; d++) s = fmaf(qs[i][d], ks[j][d], s);
        s += bias_table[rpi[e] * HEADS + h] + mrow[e];
        at[i][j] = s;
    }
    __syncthreads();

    // Softmax: one warp handles rows warp, warp+8, ...
    const int warp = tid >> 5, lane = tid & 31;
    for (int i = warp; i < WIN; i += 8) {
        float a0 = at[i][lane], a1 = at[i][lane + 32];
        float m = fmaxf(a0, a1);
        #pragma unroll
        for (int o = 16; o; o >>= 1) m = fmaxf(m, __shfl_xor_sync(0xffffffffu, m, o));
        float e0 = __expf(a0 - m), e1 = __expf(a1 - m);
        float s = e0 + e1;
        #pragma unroll
        for (int o = 16; o; o >>= 1) s += __shfl_xor_sync(0xffffffffu, s, o);
        const float rinv = 1.0f / s;
        at[i][lane] = e0 * rinv;
        at[i][lane + 32] = e1 * rinv;
    }
    __syncthreads();

    // out = attn @ v  -> g_ao[(b*WIN+i)*DIM + h*HD + d]
    float* aop = g_ao + (size_t)b * WIN * DIM + h * HD;
    for (int e = tid; e < WIN * HD; e += 256) {
        const int i = e >> 5, d = e & 31;
        float s = 0.f;
        #pragma unroll
        for (int j = 0; j < WIN; j++) s = fmaf(at[i][j], vs[j][d], s);
        aop[(size_t)i * DIM + d] = s;
    }
}

// ---------------------------------------------------------------------------
// GEMM 2: out = g_ao @ proj_w^T + proj_b   (131072 x 256 x 256)
// ---------------------------------------------------------------------------
__global__ void proj_gemm_kernel(const float* __restrict__ W,
                                 const float* __restrict__ bias,
                                 float* __restrict__ out)
{
    const int K = DIM;
    __shared__ float As[16][64];
    __shared__ float Bs[16][64];

    const int rowBase = blockIdx.y * 64;
    const int colBase = blockIdx.x * 64;
    const int tid = threadIdx.x;
    const int tx = tid & 15;
    const int ty = tid >> 4;

    float acc[4][4] = {};

    const int r   = tid >> 2;
    const int kk0 = (tid & 3) << 2;

    for (int kb = 0; kb < K; kb += 16) {
        float4 a4 = *(const float4*)&g_ao[(size_t)(rowBase + r) * K + kb + kk0];
        As[kk0 + 0][r] = a4.x; As[kk0 + 1][r] = a4.y;
        As[kk0 + 2][r] = a4.z; As[kk0 + 3][r] = a4.w;
        float4 b4 = *(const float4*)&W[(size_t)(colBase + r) * K + kb + kk0];
        Bs[kk0 + 0][r] = b4.x; Bs[kk0 + 1][r] = b4.y;
        Bs[kk0 + 2][r] = b4.z; Bs[kk0 + 3][r] = b4.w;
        __syncthreads();

        #pragma unroll
        for (int kk = 0; kk < 16; kk++) {
            float4 ra = *(const float4*)&As[kk][ty << 2];
            float4 rb = *(const float4*)&Bs[kk][tx << 2];
            float rav[4] = {ra.x, ra.y, ra.z, ra.w};
            float rbv[4] = {rb.x, rb.y, rb.z, rb.w};
            #pragma unroll
            for (int i = 0; i < 4; i++)
                #pragma unroll
                for (int j = 0; j < 4; j++)
                    acc[i][j] = fmaf(rav[i], rbv[j], acc[i][j]);
        }
        __syncthreads();
    }

    #pragma unroll
    for (int i = 0; i < 4; i++) {
        const int row = rowBase + (ty << 2) + i;
        #pragma unroll
        for (int j = 0; j < 4; j++) {
            const int col = colBase + (tx << 2) + j;
            out[(size_t)row * DIM + col] = acc[i][j] + bias[col];
        }
    }
}

// ---------------------------------------------------------------------------
// Launch. Input order (metadata): x, mask, qkv_w, qkv_b, proj_w, proj_b,
// logit_scale, rel_bias_table, rel_pos_index
// ---------------------------------------------------------------------------
extern "C" void kernel_launch(void* const* d_in, const int* in_sizes, int n_in,
                              void* d_out, int out_size)
{
    const float* x        = (const float*)d_in[0];
    const float* mask     = (const float*)d_in[1];
    const float* qkv_w    = (const float*)d_in[2];
    const float* qkv_b    = (const float*)d_in[3];
    const float* proj_w   = (const float*)d_in[4];
    const float* proj_b   = (const float*)d_in[5];
    const float* lscale   = (const float*)d_in[6];
    const float* btable   = (const float*)d_in[7];
    const int*   rpi      = (const int*)d_in[8];
    float* out = (float*)d_out;

    // 1) QKV projection: C[131072 x 768]
    {
        dim3 grid(QKV_N / 64, MROWS / 64);
        qkv_gemm_kernel<<<grid, 256>>>(x, qkv_w, qkv_b);
    }
    // 2) Attention per (window, head)
    {
        attn_kernel<<<NWIN * HEADS, 256>>>(mask, lscale, btable, rpi);
    }
    // 3) Output projection: C[131072 x 256]
    {
        dim3 grid(DIM / 64, MROWS / 64);
        proj_gemm_kernel<<<grid, 256>>>(proj_w, proj_b, out);
    }
}

// round 2
// speedup vs baseline: 1.8582x; 1.8582x over previous
#include <cuda_runtime.h>
#include <cuda_bf16.h>
#include <cstdint>

// Problem constants
#define NWIN   2048
#define WIN    64
#define DIM    256
#define HEADS  8
#define HD     32
#define NMASK  256
#define QKV_N  768
#define MROWS  (NWIN*WIN)  // 131072

// Scratch (allocation-free: __device__ globals)
__device__ float g_q[(size_t)NWIN*HEADS*WIN*HD];
__device__ float g_k[(size_t)NWIN*HEADS*WIN*HD];
__device__ float g_v[(size_t)NWIN*HEADS*WIN*HD];
__device__ float g_ao[(size_t)NWIN*WIN*DIM];

__device__ __forceinline__ unsigned f2tf32(float f) {
    unsigned r;
    asm("cvt.rna.tf32.f32 %0, %1;" : "=r"(r) : "f"(f));
    return r;
}

__device__ __forceinline__ void mma_tf32(float c[4],
                                         unsigned a0, unsigned a1, unsigned a2, unsigned a3,
                                         unsigned b0, unsigned b1) {
    asm volatile(
        "mma.sync.aligned.m16n8k8.row.col.f32.tf32.tf32.f32 "
        "{%0,%1,%2,%3}, {%4,%5,%6,%7}, {%8,%9}, {%0,%1,%2,%3};"
        : "+f"(c[0]), "+f"(c[1]), "+f"(c[2]), "+f"(c[3])
        : "r"(a0), "r"(a1), "r"(a2), "r"(a3), "r"(b0), "r"(b1));
}

// ---------------------------------------------------------------------------
// Tensor-core GEMM: C[M x N] = A[M x K] @ W[N x K]^T + bias, K=256.
// Block tile 128(M) x 64(N), BK=32, 256 threads = 8 warps (4m x 2n), each
// warp 32x32 = 2 m-atoms x 4 n-atoms of m16n8k8.
// QKV=true: scatter into g_q/g_k/g_v (b,h,n,d). QKV=false: write out + bias.
// ---------------------------------------------------------------------------
#define SA 36  // smem row stride (words) -> conflict-free fragment LDS

template<bool QKV>
__global__ void __launch_bounds__(256) mma_gemm(const float* __restrict__ A,
                                                const float* __restrict__ W,
                                                const float* __restrict__ bias,
                                                float* __restrict__ out)
{
    const int K = DIM;
    __shared__ unsigned As[128 * SA];
    __shared__ unsigned Bs[64 * SA];

    const int rowBase = blockIdx.y * 128;
    const int colBase = blockIdx.x * 64;
    const int tid  = threadIdx.x;
    const int lane = tid & 31;
    const int warp = tid >> 5;
    const int warpM = warp >> 1;     // 0..3
    const int warpN = warp & 1;      // 0..1
    const int g  = lane >> 2;        // groupID 0..7
    const int tg = lane & 3;         // threadID_in_group

    float acc[2][4][4] = {};         // [m-atom][n-atom][c0..c3]

    // global load coords
    const int ar = tid >> 1;                 // 0..127
    const int ac = (tid & 1) * 16;           // 0 or 16
    const int br = tid >> 2;                 // 0..63
    const int bc = (tid & 3) * 8;            // 0,8,16,24

    for (int kb = 0; kb < K; kb += 32) {
        // A tile 128x32 (tf32 in smem)
        #pragma unroll
        for (int i = 0; i < 4; i++) {
            float4 v = *(const float4*)&A[(size_t)(rowBase + ar) * K + kb + ac + 4 * i];
            unsigned* p = &As[ar * SA + ac + 4 * i];
            p[0] = f2tf32(v.x); p[1] = f2tf32(v.y); p[2] = f2tf32(v.z); p[3] = f2tf32(v.w);
        }
        // B tile 64x32
        #pragma unroll
        for (int i = 0; i < 2; i++) {
            float4 v = *(const float4*)&W[(size_t)(colBase + br) * K + kb + bc + 4 * i];
            unsigned* p = &Bs[br * SA + bc + 4 * i];
            p[0] = f2tf32(v.x); p[1] = f2tf32(v.y); p[2] = f2tf32(v.z); p[3] = f2tf32(v.w);
        }
        __syncthreads();

        #pragma unroll
        for (int ks = 0; ks < 4; ks++) {
            const int k0 = ks * 8;
            unsigned a[2][4];
            #pragma unroll
            for (int am = 0; am < 2; am++) {
                const int m0 = warpM * 32 + am * 16;
                a[am][0] = As[(m0 + g)     * SA + k0 + tg];
                a[am][1] = As[(m0 + g + 8) * SA + k0 + tg];
                a[am][2] = As[(m0 + g)     * SA + k0 + tg + 4];
                a[am][3] = As[(m0 + g + 8) * SA + k0 + tg + 4];
            }
            #pragma unroll
            for (int an = 0; an < 4; an++) {
                const int n0 = warpN * 32 + an * 8;
                unsigned b0 = Bs[(n0 + g) * SA + k0 + tg];
                unsigned b1 = Bs[(n0 + g) * SA + k0 + tg + 4];
                mma_tf32(acc[0][an], a[0][0], a[0][1], a[0][2], a[0][3], b0, b1);
                mma_tf32(acc[1][an], a[1][0], a[1][1], a[1][2], a[1][3], b0, b1);
            }
        }
        __syncthreads();
    }

    // Epilogue
    #pragma unroll
    for (int am = 0; am < 2; am++) {
        #pragma unroll
        for (int an = 0; an < 4; an++) {
            const int col = colBase + warpN * 32 + an * 8 + 2 * tg;
            const float bi0 = bias[col], bi1 = bias[col + 1];
            #pragma unroll
            for (int half = 0; half < 2; half++) {
                const int row = rowBase + warpM * 32 + am * 16 + g + 8 * half;
                float2 v;
                v.x = acc[am][an][2 * half]     + bi0;
                v.y = acc[am][an][2 * half + 1] + bi1;
                if (QKV) {
                    const int b = row >> 6, n = row & 63;
                    const int which = col >> 8;
                    const int h = (col >> 5) & 7;
                    const int d = col & 31;
                    float* dst = (which == 0) ? g_q : (which == 1) ? g_k : g_v;
                    *(float2*)&dst[((((size_t)b * HEADS + h) * WIN) + n) * HD + d] = v;
                } else {
                    *(float2*)&out[(size_t)row * DIM + col] = v;
                }
            }
        }
    }
}

// ---------------------------------------------------------------------------
// Attention: one block per (window b, head h). 256 threads. (unchanged)
// ---------------------------------------------------------------------------
__global__ void attn_kernel(const float* __restrict__ mask,
                            const float* __restrict__ logit_scale,
                            const float* __restrict__ bias_table,
                            const int*   __restrict__ rpi)
{
    const int bh = blockIdx.x;
    const int b  = bh >> 3;
    const int h  = bh & 7;
    const int tid = threadIdx.x;

    __shared__ float qs[WIN][HD + 1];
    __shared__ float ks[WIN][HD + 1];
    __shared__ float vs[WIN][HD + 1];
    __shared__ float at[WIN][WIN];

    const size_t base = (size_t)bh * WIN * HD;
    for (int idx = tid; idx < WIN * HD; idx += 256) {
        const int n = idx >> 5, d = idx & 31;
        qs[n][d] = g_q[base + idx];
        ks[n][d] = g_k[base + idx];
        vs[n][d] = g_v[base + idx];
    }
    __syncthreads();

    const float ls = expf(fminf(logit_scale[h], 4.6051701859880914f)); // ln(100)

    if (tid < 128) {
        const int rrow = tid & 63;
        float* rowp = (tid < 64) ? &qs[rrow][0] : &ks[rrow][0];
        float s = 0.f;
        #pragma unroll
        for (int d = 0; d < HD; d++) s += rowp[d] * rowp[d];
        float inv = 1.0f / fmaxf(sqrtf(s), 1e-12f);
        if (tid < 64) inv *= ls;
        #pragma unroll
        for (int d = 0; d < HD; d++) rowp[d] *= inv;
    }
    __syncthreads();

    const float* mrow = mask + (size_t)(b & (NMASK - 1)) * WIN * WIN;
    for (int e = tid; e < WIN * WIN; e += 256) {
        const int i = e >> 6, j = e & 63;
        float s = 0.f;
        #pragma unroll
        for (int d = 0; d < HD; d++) s = fmaf(qs[i][d], ks[j][d], s);
        s += bias_table[rpi[e] * HEADS + h] + mrow[e];
        at[i][j] = s;
    }
    __syncthreads();

    const int warp = tid >> 5, lane = tid & 31;
    for (int i = warp; i < WIN; i += 8) {
        float a0 = at[i][lane], a1 = at[i][lane + 32];
        float m = fmaxf(a0, a1);
        #pragma unroll
        for (int o = 16; o; o >>= 1) m = fmaxf(m, __shfl_xor_sync(0xffffffffu, m, o));
        float e0 = __expf(a0 - m), e1 = __expf(a1 - m);
        float s = e0 + e1;
        #pragma unroll
        for (int o = 16; o; o >>= 1) s += __shfl_xor_sync(0xffffffffu, s, o);
        const float rinv = 1.0f / s;
        at[i][lane] = e0 * rinv;
        at[i][lane + 32] = e1 * rinv;
    }
    __syncthreads();

    float* aop = g_ao + (size_t)b * WIN * DIM + h * HD;
    for (int e = tid; e < WIN * HD; e += 256) {
        const int i = e >> 5, d = e & 31;
        float s = 0.f;
        #pragma unroll
        for (int j = 0; j < WIN; j++) s = fmaf(at[i][j], vs[j][d], s);
        aop[(size_t)i * DIM + d] = s;
    }
}

// ---------------------------------------------------------------------------
extern "C" void kernel_launch(void* const* d_in, const int* in_sizes, int n_in,
                              void* d_out, int out_size)
{
    const float* x        = (const float*)d_in[0];
    const float* mask     = (const float*)d_in[1];
    const float* qkv_w    = (const float*)d_in[2];
    const float* qkv_b    = (const float*)d_in[3];
    const float* proj_w   = (const float*)d_in[4];
    const float* proj_b   = (const float*)d_in[5];
    const float* lscale   = (const float*)d_in[6];
    const float* btable   = (const float*)d_in[7];
    const int*   rpi      = (const int*)d_in[8];
    float* out = (float*)d_out;

    // 1) QKV projection (tf32 tensor cores): C[131072 x 768]
    {
        dim3 grid(QKV_N / 64, MROWS / 128);
        mma_gemm<true><<<grid, 256>>>(x, qkv_w, qkv_b, nullptr);
    }
    // 2) Attention per (window, head)
    {
        attn_kernel<<<NWIN * HEADS, 256>>>(mask, lscale, btable, rpi);
    }
    // 3) Output projection (tf32 tensor cores): C[131072 x 256]
    {
        float* ao = nullptr;
        cudaGetSymbolAddress((void**)&ao, g_ao);
        dim3 grid(DIM / 64, MROWS / 128);
        mma_gemm<false><<<grid, 256>>>(ao, proj_w, proj_b, out);
    }
}

// round 3
// speedup vs baseline: 3.3645x; 1.8106x over previous
#include <cuda_runtime.h>
#include <cuda_bf16.h>
#include <cstdint>

#define NWIN   2048
#define WIN    64
#define DIM    256
#define HEADS  8
#define HD     32
#define NMASK  256
#define QKV_N  768
#define MROWS  (NWIN*WIN)  // 131072

__device__ float g_q[(size_t)NWIN*HEADS*WIN*HD];
__device__ float g_k[(size_t)NWIN*HEADS*WIN*HD];
__device__ float g_v[(size_t)NWIN*HEADS*WIN*HD];
__device__ float g_ao[(size_t)NWIN*WIN*DIM];

__device__ __forceinline__ unsigned f2tf32(float f) {
    unsigned r;
    asm("cvt.rna.tf32.f32 %0, %1;" : "=r"(r) : "f"(f));
    return r;
}

__device__ __forceinline__ void mma_tf32(float c[4],
                                         unsigned a0, unsigned a1, unsigned a2, unsigned a3,
                                         unsigned b0, unsigned b1) {
    asm volatile(
        "mma.sync.aligned.m16n8k8.row.col.f32.tf32.tf32.f32 "
        "{%0,%1,%2,%3}, {%4,%5,%6,%7}, {%8,%9}, {%0,%1,%2,%3};"
        : "+f"(c[0]), "+f"(c[1]), "+f"(c[2]), "+f"(c[3])
        : "r"(a0), "r"(a1), "r"(a2), "r"(a3), "r"(b0), "r"(b1));
}

// ---------------------------------------------------------------------------
// Tensor-core GEMM: C[M x N] = A[M x K] @ W[N x K]^T + bias, K=256.
// Block tile 128x128, 4 warps (2m x 2n), warp tile 64x64 (4 m-atoms x 8 n-atoms).
// ---------------------------------------------------------------------------
#define SA 36

template<bool QKV>
__global__ void __launch_bounds__(128, 2) mma_gemm(const float* __restrict__ A,
                                                   const float* __restrict__ W,
                                                   const float* __restrict__ bias,
                                                   float* __restrict__ out)
{
    const int K = DIM;
    __shared__ unsigned As[128 * SA];
    __shared__ unsigned Bs[128 * SA];

    const int rowBase = blockIdx.y * 128;
    const int colBase = blockIdx.x * 128;
    const int tid  = threadIdx.x;
    const int lane = tid & 31;
    const int warp = tid >> 5;       // 0..3
    const int warpM = warp >> 1;     // 0..1
    const int warpN = warp & 1;      // 0..1
    const int g  = lane >> 2;        // 0..7
    const int tg = lane & 3;         // 0..3
    const int m0 = warpM * 64;
    const int n0 = warpN * 64;

    float acc[4][8][4] = {};         // [m-atom][n-atom][c]

    for (int kb = 0; kb < K; kb += 32) {
        // load A tile 128x32 and B tile 128x32 (1024 float4 each, 8 per thread)
        #pragma unroll
        for (int i = 0; i < 8; i++) {
            const int idx = tid + 128 * i;
            const int r = idx >> 3, c4 = idx & 7;
            float4 v = *(const float4*)&A[(size_t)(rowBase + r) * K + kb + c4 * 4];
            uint4 u = make_uint4(f2tf32(v.x), f2tf32(v.y), f2tf32(v.z), f2tf32(v.w));
            *(uint4*)&As[r * SA + c4 * 4] = u;
            float4 w = *(const float4*)&W[(size_t)(colBase + r) * K + kb + c4 * 4];
            uint4 uw = make_uint4(f2tf32(w.x), f2tf32(w.y), f2tf32(w.z), f2tf32(w.w));
            *(uint4*)&Bs[r * SA + c4 * 4] = uw;
        }
        __syncthreads();

        #pragma unroll
        for (int ks = 0; ks < 4; ks++) {
            const int k0 = ks * 8;
            unsigned a[4][4];
            #pragma unroll
            for (int am = 0; am < 4; am++) {
                const int mr = m0 + am * 16;
                a[am][0] = As[(mr + g)     * SA + k0 + tg];
                a[am][1] = As[(mr + g + 8) * SA + k0 + tg];
                a[am][2] = As[(mr + g)     * SA + k0 + tg + 4];
                a[am][3] = As[(mr + g + 8) * SA + k0 + tg + 4];
            }
            unsigned bf[8][2];
            #pragma unroll
            for (int an = 0; an < 8; an++) {
                const int nr = n0 + an * 8;
                bf[an][0] = Bs[(nr + g) * SA + k0 + tg];
                bf[an][1] = Bs[(nr + g) * SA + k0 + tg + 4];
            }
            #pragma unroll
            for (int am = 0; am < 4; am++)
                #pragma unroll
                for (int an = 0; an < 8; an++)
                    mma_tf32(acc[am][an], a[am][0], a[am][1], a[am][2], a[am][3],
                             bf[an][0], bf[an][1]);
        }
        __syncthreads();
    }

    // Epilogue
    #pragma unroll
    for (int am = 0; am < 4; am++) {
        #pragma unroll
        for (int an = 0; an < 8; an++) {
            const int col = colBase + n0 + an * 8 + 2 * tg;
            const float bi0 = bias[col], bi1 = bias[col + 1];
            #pragma unroll
            for (int half = 0; half < 2; half++) {
                const int row = rowBase + m0 + am * 16 + g + 8 * half;
                float2 v;
                v.x = acc[am][an][2 * half]     + bi0;
                v.y = acc[am][an][2 * half + 1] + bi1;
                if (QKV) {
                    const int b = row >> 6, n = row & 63;
                    const int which = col >> 8;
                    const int h = (col >> 5) & 7;
                    const int d = col & 31;
                    float* dst = (which == 0) ? g_q : (which == 1) ? g_k : g_v;
                    *(float2*)&dst[((((size_t)b * HEADS + h) * WIN) + n) * HD + d] = v;
                } else {
                    *(float2*)&out[(size_t)row * DIM + col] = v;
                }
            }
        }
    }
}

// ---------------------------------------------------------------------------
// Attention: one block per (window b, head h). 256 threads, register-tiled.
// ---------------------------------------------------------------------------
#define SP 36  // smem pitch for q/k/v rows (words): 16B-aligned, conflict-free

__global__ void __launch_bounds__(256) attn_kernel(const float* __restrict__ mask,
                            const float* __restrict__ logit_scale,
                            const float* __restrict__ bias_table,
                            const int*   __restrict__ rpi)
{
    const int bh = blockIdx.x;
    const int b  = bh >> 3;
    const int h  = bh & 7;
    const int tid = threadIdx.x;

    __shared__ float qs[WIN][SP];
    __shared__ float ks[WIN][SP];
    __shared__ float vs[WIN][SP];
    __shared__ float at[WIN][WIN];

    // Load q,k,v tiles (64x32 each) as float4
    const size_t base = (size_t)bh * WIN * HD;
    for (int idx = tid; idx < 512; idx += 256) {
        const int n = idx >> 3, c4 = (idx & 7) * 4;
        *(float4*)&qs[n][c4] = *(const float4*)&g_q[base + n * HD + c4];
        *(float4*)&ks[n][c4] = *(const float4*)&g_k[base + n * HD + c4];
        *(float4*)&vs[n][c4] = *(const float4*)&g_v[base + n * HD + c4];
    }
    __syncthreads();

    const float ls = expf(fminf(logit_scale[h], 4.6051701859880914f)); // ln(100)

    // Normalize rows of q (with scale) and k.
    if (tid < 128) {
        const int rrow = tid & 63;
        float* rowp = (tid < 64) ? &qs[rrow][0] : &ks[rrow][0];
        float s = 0.f;
        #pragma unroll
        for (int d = 0; d < HD; d++) s += rowp[d] * rowp[d];
        float inv = 1.0f / fmaxf(sqrtf(s), 1e-12f);
        if (tid < 64) inv *= ls;
        #pragma unroll
        for (int d = 0; d < HD; d++) rowp[d] *= inv;
    }
    __syncthreads();

    // Logits: 4x4 tile per thread. rows {ty+16i}, cols {tx+16j}
    const int tx = tid & 15;
    const int ty = tid >> 4;
    {
        float lacc[4][4] = {};
        #pragma unroll
        for (int d = 0; d < HD; d += 4) {
            float4 qv[4], kv[4];
            #pragma unroll
            for (int i = 0; i < 4; i++) qv[i] = *(const float4*)&qs[ty + 16 * i][d];
            #pragma unroll
            for (int j = 0; j < 4; j++) kv[j] = *(const float4*)&ks[tx + 16 * j][d];
            #pragma unroll
            for (int i = 0; i < 4; i++)
                #pragma unroll
                for (int j = 0; j < 4; j++) {
                    lacc[i][j] = fmaf(qv[i].x, kv[j].x, lacc[i][j]);
                    lacc[i][j] = fmaf(qv[i].y, kv[j].y, lacc[i][j]);
                    lacc[i][j] = fmaf(qv[i].z, kv[j].z, lacc[i][j]);
                    lacc[i][j] = fmaf(qv[i].w, kv[j].w, lacc[i][j]);
                }
        }
        // bias gather + mask add + store
        const float* mrow = mask + (size_t)(b & (NMASK - 1)) * WIN * WIN;
        #pragma unroll
        for (int i = 0; i < 4; i++) {
            const int row = ty + 16 * i;
            #pragma unroll
            for (int j = 0; j < 4; j++) {
                const int col = tx + 16 * j;
                const int e = row * WIN + col;
                at[row][col] = lacc[i][j] + bias_table[rpi[e] * HEADS + h] + mrow[e];
            }
        }
    }
    __syncthreads();

    // Softmax: one warp per row group
    const int warp = tid >> 5, lane = tid & 31;
    for (int i = warp; i < WIN; i += 8) {
        float a0 = at[i][lane], a1 = at[i][lane + 32];
        float m = fmaxf(a0, a1);
        #pragma unroll
        for (int o = 16; o; o >>= 1) m = fmaxf(m, __shfl_xor_sync(0xffffffffu, m, o));
        float e0 = __expf(a0 - m), e1 = __expf(a1 - m);
        float s = e0 + e1;
        #pragma unroll
        for (int o = 16; o; o >>= 1) s += __shfl_xor_sync(0xffffffffu, s, o);
        const float rinv = 1.0f / s;
        at[i][lane] = e0 * rinv;
        at[i][lane + 32] = e1 * rinv;
    }
    __syncthreads();

    // out = attn @ v : thread computes rows {ty+16i} x cols {2tx, 2tx+1}
    {
        float oacc[4][2] = {};
        #pragma unroll 4
        for (int j = 0; j < WIN; j += 4) {
            float4 av[4];
            #pragma unroll
            for (int i = 0; i < 4; i++) av[i] = *(const float4*)&at[ty + 16 * i][j];
            float2 vv[4];
            #pragma unroll
            for (int jj = 0; jj < 4; jj++) vv[jj] = *(const float2*)&vs[j + jj][2 * tx];
            #pragma unroll
            for (int i = 0; i < 4; i++) {
                oacc[i][0] = fmaf(av[i].x, vv[0].x, oacc[i][0]);
                oacc[i][1] = fmaf(av[i].x, vv[0].y, oacc[i][1]);
                oacc[i][0] = fmaf(av[i].y, vv[1].x, oacc[i][0]);
                oacc[i][1] = fmaf(av[i].y, vv[1].y, oacc[i][1]);
                oacc[i][0] = fmaf(av[i].z, vv[2].x, oacc[i][0]);
                oacc[i][1] = fmaf(av[i].z, vv[2].y, oacc[i][1]);
                oacc[i][0] = fmaf(av[i].w, vv[3].x, oacc[i][0]);
                oacc[i][1] = fmaf(av[i].w, vv[3].y, oacc[i][1]);
            }
        }
        float* aop = g_ao + (size_t)b * WIN * DIM + h * HD;
        #pragma unroll
        for (int i = 0; i < 4; i++) {
            const int row = ty + 16 * i;
            *(float2*)&aop[(size_t)row * DIM + 2 * tx] = *(float2*)&oacc[i][0];
        }
    }
}

// ---------------------------------------------------------------------------
extern "C" void kernel_launch(void* const* d_in, const int* in_sizes, int n_in,
                              void* d_out, int out_size)
{
    const float* x        = (const float*)d_in[0];
    const float* mask     = (const float*)d_in[1];
    const float* qkv_w    = (const float*)d_in[2];
    const float* qkv_b    = (const float*)d_in[3];
    const float* proj_w   = (const float*)d_in[4];
    const float* proj_b   = (const float*)d_in[5];
    const float* lscale   = (const float*)d_in[6];
    const float* btable   = (const float*)d_in[7];
    const int*   rpi      = (const int*)d_in[8];
    float* out = (float*)d_out;

    // 1) QKV projection: C[131072 x 768]
    {
        dim3 grid(QKV_N / 128, MROWS / 128);
        mma_gemm<true><<<grid, 128>>>(x, qkv_w, qkv_b, nullptr);
    }
    // 2) Attention per (window, head)
    {
        attn_kernel<<<NWIN * HEADS, 256>>>(mask, lscale, btable, rpi);
    }
    // 3) Output projection: C[131072 x 256]
    {
        float* ao = nullptr;
        cudaGetSymbolAddress((void**)&ao, g_ao);
        dim3 grid(DIM / 128, MROWS / 128);
        mma_gemm<false><<<grid, 128>>>(ao, proj_w, proj_b, out);
    }
}